// round 3
// baseline (speedup 1.0000x reference)
#include <cuda_runtime.h>
#include <math.h>

// Fixed problem shape (num_time_steps is always 8 in setup_inputs)
#define BN 8
#define XN 128
#define YN 128
#define YHN 65
#define WCH 24
#define DL 4
#define TSTEPS 8
#define NPAIR 12           // WCH/2
#define PTS (XN*YHN)       // 8320
#define QN (BN*WCH)        // 192
#define ROWP 129           // padded row length (float2): stride ≡ 2 (mod 32) banks

// Scratch (static device arrays — no runtime allocation)
__device__ float  d_h [BN*WCH*XN*YN];   // h,   channel-major [b][c][x][y]
__device__ float  d_x1[BN*WCH*XN*YN];   // spectral branch out, channel-major
__device__ float2 d_Hf[PTS*QN];         // forward spectrum  [p][b][c], p=kx*65+ky
__device__ float2 d_Yf[PTS*QN];         // mixed spectrum    [p][b][o]

__device__ __forceinline__ float2 cmul(float2 a, float2 b){
    return make_float2(a.x*b.x - a.y*b.y, a.x*b.y + a.y*b.x);
}

__device__ __forceinline__ void fill_tw(float2* tw, int tid, int nthr){
    for (int k = tid; k < 64; k += nthr){
        float s, c;
        sincosf(-6.2831853071795864769f * (float)k / 128.f, &s, &c);
        tw[k] = make_float2(c, s);
    }
}

// In-place radix-2 DIT FFT of 128 complex points, one warp. tw[k]=exp(-2pi i k/128).
__device__ __forceinline__ void fft128(float2* a, const float2* tw, int lane, bool inv){
    #pragma unroll
    for (int e = 0; e < 4; e++){
        int i = lane + 32*e;
        int j = __brev(i) >> 25;
        if (j > i){ float2 t = a[i]; a[i] = a[j]; a[j] = t; }
    }
    __syncwarp();
    #pragma unroll
    for (int s = 1; s <= 7; s++){
        int half = 1 << (s-1);
        #pragma unroll
        for (int r = 0; r < 2; r++){
            int t  = lane + 32*r;
            int j  = t & (half-1);
            int i1 = ((t >> (s-1)) << s) + j;
            int i2 = i1 + half;
            float2 w = tw[j << (7-s)];
            if (inv) w.y = -w.y;
            float2 u = a[i1];
            float2 v = cmul(a[i2], w);
            a[i1] = make_float2(u.x+v.x, u.y+v.y);
            a[i2] = make_float2(u.x-v.x, u.y-v.y);
        }
        __syncwarp();
    }
}

// ---------------- h0 = x @ in_w + in_b (channel-major output) --------------
__global__ __launch_bounds__(256) void k_init(const float* __restrict__ x,
                                              const float* __restrict__ inw,
                                              const float* __restrict__ inb){
    int idx = blockIdx.x*256 + threadIdx.x;
    if (idx >= BN*WCH*XN*YN) return;
    int y  = idx & 127;
    int xx = (idx >> 7) & 127;
    int c  = (idx >> 14) % WCH;
    int b  = idx / (WCH*XN*YN);
    const float2 xv = *(const float2*)(x + (((size_t)(b*XN + xx))*YN + y)*2);
    d_h[idx] = inb[c] + xv.x*inw[c] + xv.y*inw[WCH + c];
}

// ---------------- fused forward 2D rFFT (per b,channel-pair plane) ---------
__global__ __launch_bounds__(512) void k_fwd(){
    extern __shared__ float2 sm[];
    float2* tw    = sm;                       // 64
    float2* plane = sm + 64;                  // [128][ROWP]
    float2* lbuf  = plane + 128*ROWP;         // [16][2][ROWP]
    int tid = threadIdx.x;
    int b = blockIdx.x / NPAIR, pr = blockIdx.x % NPAIR;
    fill_tw(tw, tid, 512);
    const float* h0 = d_h + (size_t)(b*WCH + 2*pr)*XN*YN;
    const float* h1 = h0 + (size_t)XN*YN;
    for (int idx = tid; idx < XN*YN; idx += 512){
        int x = idx >> 7, y = idx & 127;
        plane[x*ROWP + y] = make_float2(h0[idx], h1[idx]);
    }
    __syncthreads();
    int w = tid >> 5, lane = tid & 31;
    // Y-FFT: 128 packed rows, 8 per warp
    #pragma unroll
    for (int r = 0; r < 8; r++)
        fft128(plane + (w + 16*r)*ROWP, tw, lane, false);
    __syncthreads();
    // X-FFT per ky, both channels in one warp, write paired float4
    float2* lb0 = lbuf + w*2*ROWP;
    float2* lb1 = lb0 + ROWP;
    for (int ky = w; ky < YHN; ky += 16){
        int kym = (128 - ky) & 127;
        for (int k = lane; k < XN; k += 32){
            float2 zk = plane[k*ROWP + ky];
            float2 zm = plane[k*ROWP + kym];
            lb0[k] = make_float2(0.5f*(zk.x+zm.x), 0.5f*(zk.y-zm.y));
            lb1[k] = make_float2(0.5f*(zk.y+zm.y), 0.5f*(zm.x-zk.x));
        }
        __syncwarp();
        fft128(lb0, tw, lane, false);
        fft128(lb1, tw, lane, false);
        float4* dst = (float4*)(d_Hf + (size_t)ky*QN + (b*WCH + 2*pr));
        for (int k = lane; k < XN; k += 32){
            float2 a0 = lb0[k], a1 = lb1[k];
            dst[(size_t)k*65*(QN/2)] = make_float4(a0.x, a0.y, a1.x, a1.y);
        }
        __syncwarp();
    }
}

// ---------------- per-point complex channel mix ----------------------------
__device__ __forceinline__ int hsw(int q, int t){ return q*32 + ((t + q) & 31); }

__global__ __launch_bounds__(256) void k_spec(const float2* __restrict__ specw, int d){
    __shared__ float2 Hs[QN*32];   // 48KB swizzled [q][t]
    int tid = threadIdx.x;
    int p0 = blockIdx.x * 32;
    for (int idx = tid; idx < 32*QN; idx += 256){
        int t = idx / QN, q = idx - t*QN;
        Hs[hsw(q, t)] = d_Hf[(size_t)(p0 + t)*QN + q];
    }
    __syncthreads();
    int w = tid >> 5, lane = tid & 31;          // lane <-> point p0+lane
    const float2* wp = specw + (size_t)(d*576)*PTS + p0 + lane;
    float2 acc0[8], acc1[8], acc2[8];
    #pragma unroll
    for (int bb = 0; bb < 8; bb++){
        acc0[bb] = make_float2(0.f,0.f);
        acc1[bb] = make_float2(0.f,0.f);
        acc2[bb] = make_float2(0.f,0.f);
    }
    float2 wv0 = wp[(size_t)(w     )*PTS];
    float2 wv1 = wp[(size_t)(w +  8)*PTS];
    float2 wv2 = wp[(size_t)(w + 16)*PTS];
    for (int i = 0; i < WCH; i++){
        float2 hv[8];
        #pragma unroll
        for (int bb = 0; bb < 8; bb++) hv[bb] = Hs[hsw(bb*WCH + i, lane)];
        float2 nv0, nv1, nv2;
        if (i < WCH-1){
            const float2* wn = wp + (size_t)((i+1)*WCH)*PTS;
            nv0 = wn[(size_t)(w     )*PTS];
            nv1 = wn[(size_t)(w +  8)*PTS];
            nv2 = wn[(size_t)(w + 16)*PTS];
        } else { nv0 = wv0; nv1 = wv1; nv2 = wv2; }
        #pragma unroll
        for (int bb = 0; bb < 8; bb++){
            acc0[bb].x = fmaf( hv[bb].x, wv0.x, acc0[bb].x);
            acc0[bb].x = fmaf(-hv[bb].y, wv0.y, acc0[bb].x);
            acc0[bb].y = fmaf( hv[bb].x, wv0.y, acc0[bb].y);
            acc0[bb].y = fmaf( hv[bb].y, wv0.x, acc0[bb].y);
            acc1[bb].x = fmaf( hv[bb].x, wv1.x, acc1[bb].x);
            acc1[bb].x = fmaf(-hv[bb].y, wv1.y, acc1[bb].x);
            acc1[bb].y = fmaf( hv[bb].x, wv1.y, acc1[bb].y);
            acc1[bb].y = fmaf( hv[bb].y, wv1.x, acc1[bb].y);
            acc2[bb].x = fmaf( hv[bb].x, wv2.x, acc2[bb].x);
            acc2[bb].x = fmaf(-hv[bb].y, wv2.y, acc2[bb].x);
            acc2[bb].y = fmaf( hv[bb].x, wv2.y, acc2[bb].y);
            acc2[bb].y = fmaf( hv[bb].y, wv2.x, acc2[bb].y);
        }
        wv0 = nv0; wv1 = nv1; wv2 = nv2;
    }
    __syncthreads();
    #pragma unroll
    for (int bb = 0; bb < 8; bb++){
        Hs[hsw(bb*WCH + w     , lane)] = acc0[bb];
        Hs[hsw(bb*WCH + w +  8, lane)] = acc1[bb];
        Hs[hsw(bb*WCH + w + 16, lane)] = acc2[bb];
    }
    __syncthreads();
    for (int idx = tid; idx < 32*QN; idx += 256){
        int t = idx / QN, q = idx - t*QN;
        d_Yf[(size_t)(p0 + t)*QN + q] = Hs[hsw(q, t)];
    }
}

// ---------------- fused inverse 2D FFT (per b,pair plane) ------------------
__global__ __launch_bounds__(512) void k_inv(){
    extern __shared__ float2 sm[];
    float2* tw   = sm;                        // 64
    float2* g    = sm + 64;                   // [2][65][ROWP]
    float2* lbuf = g + 2*YHN*ROWP;            // [16][2][ROWP]
    int tid = threadIdx.x;
    int b = blockIdx.x / NPAIR, pr = blockIdx.x % NPAIR;
    fill_tw(tw, tid, 512);
    __syncthreads();
    int w = tid >> 5, lane = tid & 31;
    float2* lb0 = lbuf + w*2*ROWP;
    float2* lb1 = lb0 + ROWP;
    const float sc = 1.f/128.f;
    // inverse X-FFT per ky (both channels), results into g[c][ky][x]
    for (int ky = w; ky < YHN; ky += 16){
        const float4* src = (const float4*)(d_Yf + (size_t)ky*QN + (b*WCH + 2*pr));
        for (int k = lane; k < XN; k += 32){
            float4 v = src[(size_t)k*65*(QN/2)];
            lb0[k] = make_float2(v.x, v.y);
            lb1[k] = make_float2(v.z, v.w);
        }
        __syncwarp();
        fft128(lb0, tw, lane, true);
        fft128(lb1, tw, lane, true);
        float2* g0 = g + (0*YHN + ky)*ROWP;
        float2* g1 = g + (1*YHN + ky)*ROWP;
        for (int k = lane; k < XN; k += 32){
            g0[k] = make_float2(lb0[k].x*sc, lb0[k].y*sc);
            g1[k] = make_float2(lb1[k].x*sc, lb1[k].y*sc);
        }
        __syncwarp();
    }
    __syncthreads();
    // inverse Y-rFFT per x-row (packed pair), write x1 channel-major
    float* x0p = d_x1 + (size_t)(b*WCH + 2*pr)*XN*YN;
    float* x1p = x0p + (size_t)XN*YN;
    for (int xr = w; xr < XN; xr += 16){
        for (int k = lane; k < XN; k += 32){
            float2 z;
            if (k <= 64){
                float2 g0 = g[(0*YHN + k)*ROWP + xr];
                float2 g1 = g[(1*YHN + k)*ROWP + xr];
                if (k == 0 || k == 64){ g0.y = 0.f; g1.y = 0.f; }
                z = make_float2(g0.x - g1.y, g0.y + g1.x);
            } else {
                int km = 128 - k;
                float2 g0 = g[(0*YHN + km)*ROWP + xr];
                float2 g1 = g[(1*YHN + km)*ROWP + xr];
                z = make_float2(g0.x + g1.y, g1.x - g0.y);
            }
            lb0[k] = z;
        }
        __syncwarp();
        fft128(lb0, tw, lane, true);
        for (int y = lane; y < YN; y += 32){
            x0p[xr*YN + y] = lb0[y].x*sc;
            x1p[xr*YN + y] = lb0[y].y*sc;
        }
        __syncwarp();
    }
}

// ---------------- conv(1x1) + relu-combine + h update + out proj ------------
__global__ __launch_bounds__(256) void k_conv(const float* __restrict__ convw,
                                              const float* __restrict__ convb,
                                              const float* __restrict__ outw,
                                              const float* __restrict__ outb,
                                              float* __restrict__ out,
                                              int d, int t, int last){
    __shared__ float hrow[WCH*YN];     // [c][y]
    __shared__ float xrow[WCH*YN];     // [c][y]
    __shared__ float hn[YN*25];        // [y][c] padded
    __shared__ float cw[WCH*WCH];
    __shared__ float cb[WCH];
    __shared__ float ow[WCH];
    __shared__ float ob;
    int tid = threadIdx.x;
    int bx = blockIdx.x, b = bx >> 7, x = bx & 127;
    float* hpb = d_h + (size_t)b*WCH*XN*YN + (size_t)x*YN;
    const float* xpb = d_x1 + (size_t)b*WCH*XN*YN + (size_t)x*YN;
    for (int idx = tid; idx < WCH*YN; idx += 256){
        int c = idx >> 7, y = idx & 127;
        hrow[idx] = hpb[(size_t)c*XN*YN + y];
        xrow[idx] = xpb[(size_t)c*XN*YN + y];
    }
    for (int idx = tid; idx < WCH*WCH; idx += 256) cw[idx] = convw[d*WCH*WCH + idx];
    if (tid < WCH){ cb[tid] = convb[d*WCH + tid]; ow[tid] = outw[tid]; }
    if (tid == 0) ob = outb[0];
    __syncthreads();

    int y = tid >> 1, half = tid & 1, o0 = half*12;
    float acc[12];
    #pragma unroll
    for (int j = 0; j < 12; j++) acc[j] = cb[o0 + j];
    #pragma unroll
    for (int i = 0; i < WCH; i++){
        float hv = hrow[i*YN + y];
        #pragma unroll
        for (int j = 0; j < 12; j++) acc[j] = fmaf(hv, cw[i*WCH + o0 + j], acc[j]);
    }
    #pragma unroll
    for (int j = 0; j < 12; j++){
        float v = xrow[(o0 + j)*YN + y];
        hn[y*25 + o0 + j] = fmaxf(v, 0.f) + acc[j];
    }
    __syncthreads();
    for (int idx = tid; idx < WCH*YN; idx += 256){
        int c = idx >> 7, yy = idx & 127;
        hpb[(size_t)c*XN*YN + yy] = hn[yy*25 + c];
    }
    if (last){
        for (int yy = tid; yy < YN; yy += 256){
            float a = ob;
            #pragma unroll
            for (int c = 0; c < WCH; c++) a = fmaf(hn[yy*25 + c], ow[c], a);
            out[(((size_t)b*TSTEPS + t)*XN + x)*YN + yy] = a;
        }
    }
}

// ---------------------------------------------------------------------------
extern "C" void kernel_launch(void* const* d_in, const int* in_sizes, int n_in,
                              void* d_out, int out_size){
    (void)in_sizes; (void)n_in; (void)out_size;
    const float* x     = (const float*)d_in[0];
    const float* in_w  = (const float*)d_in[1];
    const float* in_b  = (const float*)d_in[2];
    const float2* specw= (const float2*)d_in[3];
    const float* convw = (const float*)d_in[4];
    const float* convb = (const float*)d_in[5];
    const float* outw  = (const float*)d_in[6];
    const float* outb  = (const float*)d_in[7];
    float* out = (float*)d_out;

    const int FWD_SMEM = (64 + 128*ROWP + 16*2*ROWP) * (int)sizeof(float2);
    const int INV_SMEM = (64 + 2*YHN*ROWP + 16*2*ROWP) * (int)sizeof(float2);
    // Unconditional (no static state): host-side attribute set, not captured.
    cudaFuncSetAttribute(k_fwd, cudaFuncAttributeMaxDynamicSharedMemorySize, FWD_SMEM);
    cudaFuncSetAttribute(k_inv, cudaFuncAttributeMaxDynamicSharedMemorySize, INV_SMEM);

    int n = BN*WCH*XN*YN;
    k_init<<<(n + 255)/256, 256>>>(x, in_w, in_b);
    for (int t = 0; t < TSTEPS; t++){
        for (int d = 0; d < DL; d++){
            k_fwd <<<BN*NPAIR, 512, FWD_SMEM>>>();
            k_spec<<<PTS/32 , 256>>>(specw, d);
            k_inv <<<BN*NPAIR, 512, INV_SMEM>>>();
            k_conv<<<BN*XN  , 256>>>(convw, convb, outw, outb, out, d, t, d == DL-1);
        }
    }
}

// round 6
// speedup vs baseline: 1.7079x; 1.7079x over previous
#include <cuda_runtime.h>
#include <math.h>

// Fixed problem shape (num_time_steps is always 8 in setup_inputs)
#define BN 8
#define XN 128
#define YN 128
#define YHN 65
#define WCH 24
#define DL 4
#define TSTEPS 8
#define NPAIR 12
#define PTS (XN*YHN)       // 8320
#define QN (BN*WCH)        // 192

// Conventions: spatial y stored BIT-REVERSED (7-bit) in d_h/d_x1.
// kx stored bit-reversed ("kxs") in d_Hf/d_Yf; k_spec maps weights via brev7.

__device__ float  d_h [BN*WCH*XN*YN];                  // [b][c][x][yb]
__device__ float  d_x1[BN*WCH*XN*YN];                  // [b][c][x][yb]
__device__ __align__(16) float4 d_Hy[BN*YHN*NPAIR*XN]; // [b][ky][pair][x] (c0,c1)
__device__ __align__(16) float4 d_Gy[BN*YHN*NPAIR*XN]; // [b][ky][pair][x]
__device__ __align__(16) float2 d_Hf[PTS*QN];          // [(kxs*65+ky)][q]
__device__ __align__(16) float2 d_Yf[PTS*QN];          // [(kxs*65+ky)][q]

__device__ __forceinline__ float2 cmul(float2 a, float2 b){
    return make_float2(fmaf(a.x,b.x,-a.y*b.y), fmaf(a.x,b.y, a.y*b.x));
}
__device__ __forceinline__ float2 cadd(float2 a, float2 b){ return make_float2(a.x+b.x, a.y+b.y); }
__device__ __forceinline__ float2 csub(float2 a, float2 b){ return make_float2(a.x-b.x, a.y-b.y); }

struct Tw { float2 w1, w1b, w2, w4, w8, w16, w32; };

template<bool INV>
__device__ __forceinline__ float2 tsel(float2 w){ return INV ? make_float2(w.x, -w.y) : w; }

__device__ __forceinline__ Tw make_tw(int l){
    Tw t; float s, c;
    const float P = -6.2831853071795864769f;
    sincosf(P*(float)l/128.f, &s, &c);       t.w1  = make_float2(c, s);   // W^l
    t.w1b = make_float2(t.w1.y, -t.w1.x);                                 // W^{l+32}
    t.w2  = cmul(t.w1, t.w1);                                             // W^{2l}
    sincosf(P*(float)(l&15)/32.f, &s, &c);   t.w4  = make_float2(c, s);   // W_32^{l&15}
    sincosf(P*(float)(l&7)/16.f,  &s, &c);   t.w8  = make_float2(c, s);   // W_16^{l&7}
    sincosf(P*(float)(l&3)/8.f,   &s, &c);   t.w16 = make_float2(c, s);   // W_8^{l&3}
    t.w32 = (l&1) ? make_float2(0.f, -1.f) : make_float2(1.f, 0.f);       // W_4^{l&1}
    return t;
}

__device__ __forceinline__ void dif_x4(float2 v[4], int m, float2 w, int l){
    #pragma unroll
    for (int r = 0; r < 4; r++){
        float2 p;
        p.x = __shfl_xor_sync(0xffffffffu, v[r].x, m);
        p.y = __shfl_xor_sync(0xffffffffu, v[r].y, m);
        v[r] = (l & m) ? cmul(csub(p, v[r]), w) : cadd(v[r], p);
    }
}
__device__ __forceinline__ void dit_x4(float2 v[4], int m, float2 w, int l){
    #pragma unroll
    for (int r = 0; r < 4; r++){
        float2 b = (l & m) ? cmul(v[r], w) : v[r];
        float2 p;
        p.x = __shfl_xor_sync(0xffffffffu, b.x, m);
        p.y = __shfl_xor_sync(0xffffffffu, b.y, m);
        v[r] = (l & m) ? csub(p, b) : cadd(b, p);
    }
}

// DIF: natural input -> bit-reversed output.
template<bool INV>
__device__ __forceinline__ void fft_dif(float2 v[4], const Tw& t, int l){
    const float2 one = make_float2(1.f, 0.f);
    float2 w1 = tsel<INV>(t.w1), w1b = tsel<INV>(t.w1b), w2 = tsel<INV>(t.w2);
    float2 tm;
    tm = csub(v[0], v[2]); v[0] = cadd(v[0], v[2]); v[2] = cmul(tm, w1);   // m=64
    tm = csub(v[1], v[3]); v[1] = cadd(v[1], v[3]); v[3] = cmul(tm, w1b);
    tm = csub(v[0], v[1]); v[0] = cadd(v[0], v[1]); v[1] = cmul(tm, w2);   // m=32
    tm = csub(v[2], v[3]); v[2] = cadd(v[2], v[3]); v[3] = cmul(tm, w2);
    dif_x4(v, 16, tsel<INV>(t.w4),  l);
    dif_x4(v,  8, tsel<INV>(t.w8),  l);
    dif_x4(v,  4, tsel<INV>(t.w16), l);
    dif_x4(v,  2, tsel<INV>(t.w32), l);
    dif_x4(v,  1, one, l);
}

// DIT: bit-reversed input -> natural output.
template<bool INV>
__device__ __forceinline__ void fft_dit(float2 v[4], const Tw& t, int l){
    const float2 one = make_float2(1.f, 0.f);
    dit_x4(v,  1, one, l);
    dit_x4(v,  2, tsel<INV>(t.w32), l);
    dit_x4(v,  4, tsel<INV>(t.w16), l);
    dit_x4(v,  8, tsel<INV>(t.w8),  l);
    dit_x4(v, 16, tsel<INV>(t.w4),  l);
    float2 w1 = tsel<INV>(t.w1), w1b = tsel<INV>(t.w1b), w2 = tsel<INV>(t.w2);
    float2 b;
    b = cmul(v[1], w2);  v[1] = csub(v[0], b); v[0] = cadd(v[0], b);       // m=32
    b = cmul(v[3], w2);  v[3] = csub(v[2], b); v[2] = cadd(v[2], b);
    b = cmul(v[2], w1);  v[2] = csub(v[0], b); v[0] = cadd(v[0], b);       // m=64
    b = cmul(v[3], w1b); v[3] = csub(v[1], b); v[1] = cadd(v[1], b);
}

__device__ __forceinline__ int brev7(int i){ return (int)(__brev((unsigned)i) >> 25); }

// ---------------- h0 = x @ in_w + in_b, y stored bit-reversed --------------
__global__ __launch_bounds__(256) void k_init(const float* __restrict__ x,
                                              const float* __restrict__ inw,
                                              const float* __restrict__ inb){
    int idx = blockIdx.x*256 + threadIdx.x;
    if (idx >= BN*WCH*XN*YN) return;
    int y  = idx & 127;
    int xx = (idx >> 7) & 127;
    int c  = (idx >> 14) % WCH;
    int b  = idx / (WCH*XN*YN);
    const float2 xv = *(const float2*)(x + (((size_t)(b*XN + xx))*YN + y)*2);
    float val = inb[c] + xv.x*inw[c] + xv.y*inw[WCH + c];
    d_h[(((size_t)(b*WCH + c)*XN + xx))*YN + brev7(y)] = val;
}

// ---- stage A: Y-rFFT (packed channel pair), one warp per (b,x,pair) -------
__global__ __launch_bounds__(256) void k_ffty(){
    int tid = threadIdx.x, wl = tid >> 5, l = tid & 31;
    int wid = blockIdx.x*8 + wl;                  // 12288 warps
    int pr = wid % NPAIR;
    int x  = (wid / NPAIR) % XN;
    int b  = wid / (NPAIR*XN);
    Tw tw = make_tw(l);
    const float* h0 = d_h + ((size_t)(b*WCH + 2*pr)*XN + x)*YN;
    const float* h1 = h0 + (size_t)XN*YN;
    float2 v[4];
    #pragma unroll
    for (int r = 0; r < 4; r++){
        int p = r*32 + l;
        v[r] = make_float2(h0[p], h1[p]);
    }
    fft_dit<false>(v, tw, l);                     // natural ky = r*32+l
    int srcl = (32 - l) & 31;
    float2 s3, s2;
    s3.x = __shfl_sync(0xffffffffu, v[3].x, srcl);
    s3.y = __shfl_sync(0xffffffffu, v[3].y, srcl);
    s2.x = __shfl_sync(0xffffffffu, v[2].x, srcl);
    s2.y = __shfl_sync(0xffffffffu, v[2].y, srcl);
    float2 zm0 = (l == 0) ? v[0] : s3;            // partner of ky=l
    float2 zm1 = (l == 0) ? s3   : s2;            // partner of ky=32+l
    float4* hy = d_Hy + ((size_t)b*YHN*NPAIR + pr)*XN + x;   // + ky*NPAIR*XN
    float2 zk;
    zk = v[0];                                    // ky = l
    hy[(size_t)l*NPAIR*XN] = make_float4(
        0.5f*(zk.x+zm0.x), 0.5f*(zk.y-zm0.y),
        0.5f*(zk.y+zm0.y), 0.5f*(zm0.x-zk.x));
    zk = v[1];                                    // ky = 32+l
    hy[(size_t)(32+l)*NPAIR*XN] = make_float4(
        0.5f*(zk.x+zm1.x), 0.5f*(zk.y-zm1.y),
        0.5f*(zk.y+zm1.y), 0.5f*(zm1.x-zk.x));
    if (l == 0){                                  // ky = 64 (self-paired)
        zk = v[2];
        hy[(size_t)64*NPAIR*XN] = make_float4(zk.x, 0.f, zk.y, 0.f);
    }
}

// ---- stage B: X-FFT (complex, both channels), warp per (b,ky,pair) --------
__global__ __launch_bounds__(256) void k_fftx(){
    int tid = threadIdx.x, wl = tid >> 5, l = tid & 31;
    int wid = blockIdx.x*8 + wl;                  // 6240 warps
    int pr = wid % NPAIR;
    int ky = (wid / NPAIR) % YHN;
    int b  = wid / (NPAIR*YHN);
    Tw tw = make_tw(l);
    const float4* src = d_Hy + (((size_t)b*YHN + ky)*NPAIR + pr)*XN;
    float2 v[4], u[4];
    #pragma unroll
    for (int r = 0; r < 4; r++){
        float4 f = src[r*32 + l];
        v[r] = make_float2(f.x, f.y);
        u[r] = make_float2(f.z, f.w);
    }
    fft_dif<false>(v, tw, l);
    fft_dif<false>(u, tw, l);
    int q0 = b*WCH + 2*pr;
    #pragma unroll
    for (int r = 0; r < 4; r++){
        int kxs = r*32 + l;
        *(float4*)(d_Hf + ((size_t)kxs*YHN + ky)*QN + q0)
            = make_float4(v[r].x, v[r].y, u[r].x, u[r].y);
    }
}

// ---------------- per-point complex channel mix ----------------------------
__device__ __forceinline__ int hsw(int q, int t){ return q*32 + ((t + q) & 31); }

__global__ __launch_bounds__(256) void k_spec(const float2* __restrict__ specw, int d){
    __shared__ float2 Hs[QN*32];   // 48KB swizzled [q][t]
    int tid = threadIdx.x;
    int p0 = blockIdx.x * 32;
    for (int idx = tid; idx < 32*QN; idx += 256){
        int t = idx / QN, q = idx - t*QN;
        Hs[hsw(q, t)] = d_Hf[(size_t)(p0 + t)*QN + q];
    }
    __syncthreads();
    int w = tid >> 5, lane = tid & 31;
    int p   = p0 + lane;
    int kxs = p / 65;
    int ky  = p - kxs*65;
    int pb  = brev7(kxs)*65 + ky;                 // true weight column
    const float2* wp = specw + (size_t)(d*576)*PTS + pb;
    float2 acc0[8], acc1[8], acc2[8];
    #pragma unroll
    for (int bb = 0; bb < 8; bb++){
        acc0[bb] = make_float2(0.f,0.f);
        acc1[bb] = make_float2(0.f,0.f);
        acc2[bb] = make_float2(0.f,0.f);
    }
    float2 wv0 = wp[(size_t)(w     )*PTS];
    float2 wv1 = wp[(size_t)(w +  8)*PTS];
    float2 wv2 = wp[(size_t)(w + 16)*PTS];
    for (int i = 0; i < WCH; i++){
        float2 hv[8];
        #pragma unroll
        for (int bb = 0; bb < 8; bb++) hv[bb] = Hs[hsw(bb*WCH + i, lane)];
        float2 nv0, nv1, nv2;
        if (i < WCH-1){
            const float2* wn = wp + (size_t)((i+1)*WCH)*PTS;
            nv0 = wn[(size_t)(w     )*PTS];
            nv1 = wn[(size_t)(w +  8)*PTS];
            nv2 = wn[(size_t)(w + 16)*PTS];
        } else { nv0 = wv0; nv1 = wv1; nv2 = wv2; }
        #pragma unroll
        for (int bb = 0; bb < 8; bb++){
            acc0[bb].x = fmaf( hv[bb].x, wv0.x, acc0[bb].x);
            acc0[bb].x = fmaf(-hv[bb].y, wv0.y, acc0[bb].x);
            acc0[bb].y = fmaf( hv[bb].x, wv0.y, acc0[bb].y);
            acc0[bb].y = fmaf( hv[bb].y, wv0.x, acc0[bb].y);
            acc1[bb].x = fmaf( hv[bb].x, wv1.x, acc1[bb].x);
            acc1[bb].x = fmaf(-hv[bb].y, wv1.y, acc1[bb].x);
            acc1[bb].y = fmaf( hv[bb].x, wv1.y, acc1[bb].y);
            acc1[bb].y = fmaf( hv[bb].y, wv1.x, acc1[bb].y);
            acc2[bb].x = fmaf( hv[bb].x, wv2.x, acc2[bb].x);
            acc2[bb].x = fmaf(-hv[bb].y, wv2.y, acc2[bb].x);
            acc2[bb].y = fmaf( hv[bb].x, wv2.y, acc2[bb].y);
            acc2[bb].y = fmaf( hv[bb].y, wv2.x, acc2[bb].y);
        }
        wv0 = nv0; wv1 = nv1; wv2 = nv2;
    }
    __syncthreads();
    #pragma unroll
    for (int bb = 0; bb < 8; bb++){
        Hs[hsw(bb*WCH + w     , lane)] = acc0[bb];
        Hs[hsw(bb*WCH + w +  8, lane)] = acc1[bb];
        Hs[hsw(bb*WCH + w + 16, lane)] = acc2[bb];
    }
    __syncthreads();
    for (int idx = tid; idx < 32*QN; idx += 256){
        int t = idx / QN, q = idx - t*QN;
        d_Yf[(size_t)(p0 + t)*QN + q] = Hs[hsw(q, t)];
    }
}

// ---- stage D: inverse X-FFT, warp per (b,ky,pair) -------------------------
__global__ __launch_bounds__(256) void k_ifftx(){
    int tid = threadIdx.x, wl = tid >> 5, l = tid & 31;
    int wid = blockIdx.x*8 + wl;                  // 6240 warps
    int pr = wid % NPAIR;
    int ky = (wid / NPAIR) % YHN;
    int b  = wid / (NPAIR*YHN);
    Tw tw = make_tw(l);
    int q0 = b*WCH + 2*pr;
    float2 v[4], u[4];
    #pragma unroll
    for (int r = 0; r < 4; r++){
        int kxs = r*32 + l;
        float4 f = *(const float4*)(d_Yf + ((size_t)kxs*YHN + ky)*QN + q0);
        v[r] = make_float2(f.x, f.y);
        u[r] = make_float2(f.z, f.w);
    }
    fft_dit<true>(v, tw, l);
    fft_dit<true>(u, tw, l);
    float4* dst = d_Gy + (((size_t)b*YHN + ky)*NPAIR + pr)*XN;
    #pragma unroll
    for (int r = 0; r < 4; r++)
        dst[r*32 + l] = make_float4(v[r].x, v[r].y, u[r].x, u[r].y);
}

// ---- stage E: inverse Y-rFFT (packed pair), warp per (b,x,pair) -----------
__global__ __launch_bounds__(256) void k_iffty(){
    int tid = threadIdx.x, wl = tid >> 5, l = tid & 31;
    int wid = blockIdx.x*8 + wl;                  // 12288 warps
    int pr = wid % NPAIR;
    int x  = (wid / NPAIR) % XN;
    int b  = wid / (NPAIR*XN);
    Tw tw = make_tw(l);
    const float4* gy = d_Gy + ((size_t)b*YHN*NPAIR + pr)*XN + x;  // + k*NPAIR*XN
    float2 z[4];
    {   // k = l (direct; DC imag discarded at l==0)
        float4 f = gy[(size_t)l*NPAIR*XN];
        float2 g0 = make_float2(f.x, f.y), g1 = make_float2(f.z, f.w);
        if (l == 0){ g0.y = 0.f; g1.y = 0.f; }
        z[0] = make_float2(g0.x - g1.y, g0.y + g1.x);
    }
    {   // k = 32+l (direct)
        float4 f = gy[(size_t)(32+l)*NPAIR*XN];
        z[1] = make_float2(f.x - f.w, f.y + f.z);
    }
    {   // k = 64+l: l==0 direct (Nyquist imag discarded); else mirror km=64-l
        int km = 64 - l;
        float4 f = gy[(size_t)km*NPAIR*XN];
        float2 g0 = make_float2(f.x, f.y), g1 = make_float2(f.z, f.w);
        if (l == 0){
            g0.y = 0.f; g1.y = 0.f;
            z[2] = make_float2(g0.x - g1.y, g0.y + g1.x);
        } else {
            z[2] = make_float2(g0.x + g1.y, g1.x - g0.y);
        }
    }
    {   // k = 96+l: mirror km = 32-l
        int km = 32 - l;
        float4 f = gy[(size_t)km*NPAIR*XN];
        z[3] = make_float2(f.x + f.w, f.z - f.y);
    }
    fft_dif<true>(z, tw, l);                      // output at bitrev-y storage
    const float sc = 1.f/16384.f;                 // 1/128 (X) * 1/128 (Y)
    float* x0p = d_x1 + ((size_t)(b*WCH + 2*pr)*XN + x)*YN;
    float* x1p = x0p + (size_t)XN*YN;
    #pragma unroll
    for (int r = 0; r < 4; r++){
        int p = r*32 + l;
        x0p[p] = z[r].x * sc;
        x1p[p] = z[r].y * sc;
    }
}

// ---------------- conv(1x1) + relu-combine + h update + out proj ------------
__global__ __launch_bounds__(256) void k_conv(const float* __restrict__ convw,
                                              const float* __restrict__ convb,
                                              const float* __restrict__ outw,
                                              const float* __restrict__ outb,
                                              float* __restrict__ out,
                                              int d, int t, int last){
    __shared__ float hrow[WCH*YN];
    __shared__ float xrow[WCH*YN];
    __shared__ float hn[YN*25];
    __shared__ float cw[WCH*WCH];
    __shared__ float cb[WCH];
    __shared__ float ow[WCH];
    __shared__ float ob;
    int tid = threadIdx.x;
    int bx = blockIdx.x, b = bx >> 7, x = bx & 127;
    float* hpb = d_h + (size_t)b*WCH*XN*YN + (size_t)x*YN;
    const float* xpb = d_x1 + (size_t)b*WCH*XN*YN + (size_t)x*YN;
    for (int idx = tid; idx < WCH*YN; idx += 256){
        int c = idx >> 7, y = idx & 127;
        hrow[idx] = hpb[(size_t)c*XN*YN + y];
        xrow[idx] = xpb[(size_t)c*XN*YN + y];
    }
    for (int idx = tid; idx < WCH*WCH; idx += 256) cw[idx] = convw[d*WCH*WCH + idx];
    if (tid < WCH){ cb[tid] = convb[d*WCH + tid]; ow[tid] = outw[tid]; }
    if (tid == 0) ob = outb[0];
    __syncthreads();

    int y = tid >> 1, half = tid & 1, o0 = half*12;
    float acc[12];
    #pragma unroll
    for (int j = 0; j < 12; j++) acc[j] = cb[o0 + j];
    #pragma unroll
    for (int i = 0; i < WCH; i++){
        float hv = hrow[i*YN + y];
        #pragma unroll
        for (int j = 0; j < 12; j++) acc[j] = fmaf(hv, cw[i*WCH + o0 + j], acc[j]);
    }
    #pragma unroll
    for (int j = 0; j < 12; j++){
        float v = xrow[(o0 + j)*YN + y];
        hn[y*25 + o0 + j] = fmaxf(v, 0.f) + acc[j];
    }
    __syncthreads();
    for (int idx = tid; idx < WCH*YN; idx += 256){
        int c = idx >> 7, yy = idx & 127;
        hpb[(size_t)c*XN*YN + yy] = hn[yy*25 + c];
    }
    if (last){
        for (int yy = tid; yy < YN; yy += 256){
            float a = ob;
            #pragma unroll
            for (int c = 0; c < WCH; c++) a = fmaf(hn[yy*25 + c], ow[c], a);
            out[(((size_t)b*TSTEPS + t)*XN + x)*YN + brev7(yy)] = a;
        }
    }
}

// ---------------------------------------------------------------------------
extern "C" void kernel_launch(void* const* d_in, const int* in_sizes, int n_in,
                              void* d_out, int out_size){
    (void)in_sizes; (void)n_in; (void)out_size;
    const float* x     = (const float*)d_in[0];
    const float* in_w  = (const float*)d_in[1];
    const float* in_b  = (const float*)d_in[2];
    const float2* specw= (const float2*)d_in[3];
    const float* convw = (const float*)d_in[4];
    const float* convb = (const float*)d_in[5];
    const float* outw  = (const float*)d_in[6];
    const float* outb  = (const float*)d_in[7];
    float* out = (float*)d_out;

    int n = BN*WCH*XN*YN;
    k_init<<<(n + 255)/256, 256>>>(x, in_w, in_b);
    for (int t = 0; t < TSTEPS; t++){
        for (int d = 0; d < DL; d++){
            k_ffty <<<BN*XN*NPAIR/8 , 256>>>();   // 1536 blocks
            k_fftx <<<BN*YHN*NPAIR/8, 256>>>();   // 780 blocks
            k_spec <<<PTS/32        , 256>>>(specw, d);
            k_ifftx<<<BN*YHN*NPAIR/8, 256>>>();   // 780 blocks
            k_iffty<<<BN*XN*NPAIR/8 , 256>>>();   // 1536 blocks
            k_conv <<<BN*XN         , 256>>>(convw, convb, outw, outb, out, d, t, d == DL-1);
        }
    }
}

// round 8
// speedup vs baseline: 1.9625x; 1.1490x over previous
#include <cuda_runtime.h>
#include <math.h>

#define BN 8
#define XN 128
#define YN 128
#define YHN 65
#define WCH 24
#define DL 4
#define TSTEPS 8
#define NPAIR 12
#define PTS (XN*YHN)       // 8320
#define QN (BN*WCH)        // 192

// Conventions: spatial y stored BIT-REVERSED (7-bit) in d_h.
// kx stored bit-reversed ("kxs") in d_Hf/d_Yf; k_spec maps weights via brev7.

__device__ float  d_h [BN*WCH*XN*YN];                  // [b][c][x][yb]
__device__ __align__(16) float4 d_Hy[BN*YHN*NPAIR*XN]; // [b][ky][pair][x]
__device__ __align__(16) float4 d_Gy[BN*YHN*NPAIR*XN]; // [b][ky][pair][x]
__device__ __align__(16) float2 d_Hf[PTS*QN];          // [(kxs*65+ky)][q]
__device__ __align__(16) float2 d_Yf[PTS*QN];          // [(kxs*65+ky)][q]

__device__ __forceinline__ float2 cmul(float2 a, float2 b){
    return make_float2(fmaf(a.x,b.x,-a.y*b.y), fmaf(a.x,b.y, a.y*b.x));
}
__device__ __forceinline__ float2 cadd(float2 a, float2 b){ return make_float2(a.x+b.x, a.y+b.y); }
__device__ __forceinline__ float2 csub(float2 a, float2 b){ return make_float2(a.x-b.x, a.y-b.y); }

struct Tw { float2 w1, w1b, w2, w4, w8, w16, w32; };

template<bool INV>
__device__ __forceinline__ float2 tsel(float2 w){ return INV ? make_float2(w.x, -w.y) : w; }

__device__ __forceinline__ Tw make_tw(int l){
    Tw t; float s, c;
    const float P = -6.2831853071795864769f;
    sincosf(P*(float)l/128.f, &s, &c);       t.w1  = make_float2(c, s);
    t.w1b = make_float2(t.w1.y, -t.w1.x);
    t.w2  = cmul(t.w1, t.w1);
    sincosf(P*(float)(l&15)/32.f, &s, &c);   t.w4  = make_float2(c, s);
    sincosf(P*(float)(l&7)/16.f,  &s, &c);   t.w8  = make_float2(c, s);
    sincosf(P*(float)(l&3)/8.f,   &s, &c);   t.w16 = make_float2(c, s);
    t.w32 = (l&1) ? make_float2(0.f, -1.f) : make_float2(1.f, 0.f);
    return t;
}

__device__ __forceinline__ void dif_x4(float2 v[4], int m, float2 w, int l){
    #pragma unroll
    for (int r = 0; r < 4; r++){
        float2 p;
        p.x = __shfl_xor_sync(0xffffffffu, v[r].x, m);
        p.y = __shfl_xor_sync(0xffffffffu, v[r].y, m);
        v[r] = (l & m) ? cmul(csub(p, v[r]), w) : cadd(v[r], p);
    }
}
__device__ __forceinline__ void dit_x4(float2 v[4], int m, float2 w, int l){
    #pragma unroll
    for (int r = 0; r < 4; r++){
        float2 b = (l & m) ? cmul(v[r], w) : v[r];
        float2 p;
        p.x = __shfl_xor_sync(0xffffffffu, b.x, m);
        p.y = __shfl_xor_sync(0xffffffffu, b.y, m);
        v[r] = (l & m) ? csub(p, b) : cadd(b, p);
    }
}

template<bool INV>
__device__ __forceinline__ void fft_dif(float2 v[4], const Tw& t, int l){
    const float2 one = make_float2(1.f, 0.f);
    float2 w1 = tsel<INV>(t.w1), w1b = tsel<INV>(t.w1b), w2 = tsel<INV>(t.w2);
    float2 tm;
    tm = csub(v[0], v[2]); v[0] = cadd(v[0], v[2]); v[2] = cmul(tm, w1);
    tm = csub(v[1], v[3]); v[1] = cadd(v[1], v[3]); v[3] = cmul(tm, w1b);
    tm = csub(v[0], v[1]); v[0] = cadd(v[0], v[1]); v[1] = cmul(tm, w2);
    tm = csub(v[2], v[3]); v[2] = cadd(v[2], v[3]); v[3] = cmul(tm, w2);
    dif_x4(v, 16, tsel<INV>(t.w4),  l);
    dif_x4(v,  8, tsel<INV>(t.w8),  l);
    dif_x4(v,  4, tsel<INV>(t.w16), l);
    dif_x4(v,  2, tsel<INV>(t.w32), l);
    dif_x4(v,  1, one, l);
}

template<bool INV>
__device__ __forceinline__ void fft_dit(float2 v[4], const Tw& t, int l){
    const float2 one = make_float2(1.f, 0.f);
    dit_x4(v,  1, one, l);
    dit_x4(v,  2, tsel<INV>(t.w32), l);
    dit_x4(v,  4, tsel<INV>(t.w16), l);
    dit_x4(v,  8, tsel<INV>(t.w8),  l);
    dit_x4(v, 16, tsel<INV>(t.w4),  l);
    float2 w1 = tsel<INV>(t.w1), w1b = tsel<INV>(t.w1b), w2 = tsel<INV>(t.w2);
    float2 b;
    b = cmul(v[1], w2);  v[1] = csub(v[0], b); v[0] = cadd(v[0], b);
    b = cmul(v[3], w2);  v[3] = csub(v[2], b); v[2] = cadd(v[2], b);
    b = cmul(v[2], w1);  v[2] = csub(v[0], b); v[0] = cadd(v[0], b);
    b = cmul(v[3], w1b); v[3] = csub(v[1], b); v[1] = cadd(v[1], b);
}

__device__ __forceinline__ int brev7(int i){ return (int)(__brev((unsigned)i) >> 25); }

// Forward packed Y-FFT of one channel pair from smem row hn[yb*25 + c], write d_Hy.
__device__ __forceinline__ void ffty_pair(const float* hn, int b, int x, int pr,
                                          const Tw& tw, int l){
    float2 v[4];
    #pragma unroll
    for (int r = 0; r < 4; r++){
        int p = r*32 + l;
        v[r] = make_float2(hn[p*25 + 2*pr], hn[p*25 + 2*pr + 1]);
    }
    fft_dit<false>(v, tw, l);                     // natural ky = r*32+l
    int srcl = (32 - l) & 31;
    float2 s3, s2;
    s3.x = __shfl_sync(0xffffffffu, v[3].x, srcl);
    s3.y = __shfl_sync(0xffffffffu, v[3].y, srcl);
    s2.x = __shfl_sync(0xffffffffu, v[2].x, srcl);
    s2.y = __shfl_sync(0xffffffffu, v[2].y, srcl);
    float2 zm0 = (l == 0) ? v[0] : s3;            // partner of ky=l
    float2 zm1 = (l == 0) ? s3   : s2;            // partner of ky=32+l
    float4* hy = d_Hy + ((size_t)b*YHN*NPAIR + pr)*XN + x;
    float2 zk;
    zk = v[0];                                    // ky = l
    hy[(size_t)l*NPAIR*XN] = make_float4(
        0.5f*(zk.x+zm0.x), 0.5f*(zk.y-zm0.y),
        0.5f*(zk.y+zm0.y), 0.5f*(zm0.x-zk.x));
    zk = v[1];                                    // ky = 32+l
    hy[(size_t)(32+l)*NPAIR*XN] = make_float4(
        0.5f*(zk.x+zm1.x), 0.5f*(zk.y-zm1.y),
        0.5f*(zk.y+zm1.y), 0.5f*(zm1.x-zk.x));
    if (l == 0){                                  // ky = 64
        zk = v[2];
        hy[(size_t)64*NPAIR*XN] = make_float4(zk.x, 0.f, zk.y, 0.f);
    }
}

// ---------------- k_first: h0 = x@in_w+in_b (bitrev-y) + forward Y-FFT ------
__global__ __launch_bounds__(384) void k_first(const float* __restrict__ xin,
                                               const float* __restrict__ inw,
                                               const float* __restrict__ inb){
    __shared__ float2 xv[XN];
    __shared__ float  hn[YN*25];
    int tid = threadIdx.x, wl = tid >> 5, l = tid & 31;
    int bx = blockIdx.x, b = bx >> 7, x = bx & 127;
    if (tid < XN)
        xv[tid] = *(const float2*)(xin + (((size_t)(b*XN + x))*YN + tid)*2);
    __syncthreads();
    for (int idx = tid; idx < WCH*YN; idx += 384){
        int c = idx >> 7, yb = idx & 127;
        float2 v = xv[brev7(yb)];
        float val = inb[c] + v.x*inw[c] + v.y*inw[WCH + c];
        hn[yb*25 + c] = val;
        d_h[((size_t)(b*WCH + c)*XN + x)*YN + yb] = val;
    }
    __syncthreads();
    Tw tw = make_tw(l);
    ffty_pair(hn, b, x, wl, tw, l);
}

// ---- X-FFT (complex, both channels), warp per (b,ky,pair) -----------------
__global__ __launch_bounds__(256) void k_fftx(){
    int tid = threadIdx.x, wl = tid >> 5, l = tid & 31;
    int wid = blockIdx.x*8 + wl;
    int pr = wid % NPAIR;
    int ky = (wid / NPAIR) % YHN;
    int b  = wid / (NPAIR*YHN);
    Tw tw = make_tw(l);
    const float4* src = d_Hy + (((size_t)b*YHN + ky)*NPAIR + pr)*XN;
    float2 v[4], u[4];
    #pragma unroll
    for (int r = 0; r < 4; r++){
        float4 f = src[r*32 + l];
        v[r] = make_float2(f.x, f.y);
        u[r] = make_float2(f.z, f.w);
    }
    fft_dif<false>(v, tw, l);
    fft_dif<false>(u, tw, l);
    int q0 = b*WCH + 2*pr;
    #pragma unroll
    for (int r = 0; r < 4; r++){
        int kxs = r*32 + l;
        *(float4*)(d_Hf + ((size_t)kxs*YHN + ky)*QN + q0)
            = make_float4(v[r].x, v[r].y, u[r].x, u[r].y);
    }
}

// ---------------- per-point complex channel mix ----------------------------
__device__ __forceinline__ int hsw(int q, int t){ return q*32 + ((t + q) & 31); }

__global__ __launch_bounds__(256) void k_spec(const float2* __restrict__ specw, int d){
    __shared__ float2 Hs[QN*32];
    int tid = threadIdx.x;
    int p0 = blockIdx.x * 32;
    for (int idx = tid; idx < 32*QN; idx += 256){
        int t = idx / QN, q = idx - t*QN;
        Hs[hsw(q, t)] = d_Hf[(size_t)(p0 + t)*QN + q];
    }
    __syncthreads();
    int w = tid >> 5, lane = tid & 31;
    int p   = p0 + lane;
    int kxs = p / 65;
    int ky  = p - kxs*65;
    int pb  = brev7(kxs)*65 + ky;                 // true weight column
    const float2* wp = specw + (size_t)(d*576)*PTS + pb;
    float2 acc0[8], acc1[8], acc2[8];
    #pragma unroll
    for (int bb = 0; bb < 8; bb++){
        acc0[bb] = make_float2(0.f,0.f);
        acc1[bb] = make_float2(0.f,0.f);
        acc2[bb] = make_float2(0.f,0.f);
    }
    // software pipeline, depth 2
    float2 wv0 = wp[(size_t)(0*WCH + w     )*PTS];
    float2 wv1 = wp[(size_t)(0*WCH + w +  8)*PTS];
    float2 wv2 = wp[(size_t)(0*WCH + w + 16)*PTS];
    float2 pv0 = wp[(size_t)(1*WCH + w     )*PTS];
    float2 pv1 = wp[(size_t)(1*WCH + w +  8)*PTS];
    float2 pv2 = wp[(size_t)(1*WCH + w + 16)*PTS];
    for (int i = 0; i < WCH; i++){
        int ip = (i + 2 < WCH) ? i + 2 : WCH - 1;
        float2 qv0 = wp[(size_t)(ip*WCH + w     )*PTS];
        float2 qv1 = wp[(size_t)(ip*WCH + w +  8)*PTS];
        float2 qv2 = wp[(size_t)(ip*WCH + w + 16)*PTS];
        float2 hv[8];
        #pragma unroll
        for (int bb = 0; bb < 8; bb++) hv[bb] = Hs[hsw(bb*WCH + i, lane)];
        #pragma unroll
        for (int bb = 0; bb < 8; bb++){
            acc0[bb].x = fmaf( hv[bb].x, wv0.x, acc0[bb].x);
            acc0[bb].x = fmaf(-hv[bb].y, wv0.y, acc0[bb].x);
            acc0[bb].y = fmaf( hv[bb].x, wv0.y, acc0[bb].y);
            acc0[bb].y = fmaf( hv[bb].y, wv0.x, acc0[bb].y);
            acc1[bb].x = fmaf( hv[bb].x, wv1.x, acc1[bb].x);
            acc1[bb].x = fmaf(-hv[bb].y, wv1.y, acc1[bb].x);
            acc1[bb].y = fmaf( hv[bb].x, wv1.y, acc1[bb].y);
            acc1[bb].y = fmaf( hv[bb].y, wv1.x, acc1[bb].y);
            acc2[bb].x = fmaf( hv[bb].x, wv2.x, acc2[bb].x);
            acc2[bb].x = fmaf(-hv[bb].y, wv2.y, acc2[bb].x);
            acc2[bb].y = fmaf( hv[bb].x, wv2.y, acc2[bb].y);
            acc2[bb].y = fmaf( hv[bb].y, wv2.x, acc2[bb].y);
        }
        wv0 = pv0; wv1 = pv1; wv2 = pv2;
        pv0 = qv0; pv1 = qv1; pv2 = qv2;
    }
    __syncthreads();
    #pragma unroll
    for (int bb = 0; bb < 8; bb++){
        Hs[hsw(bb*WCH + w     , lane)] = acc0[bb];
        Hs[hsw(bb*WCH + w +  8, lane)] = acc1[bb];
        Hs[hsw(bb*WCH + w + 16, lane)] = acc2[bb];
    }
    __syncthreads();
    for (int idx = tid; idx < 32*QN; idx += 256){
        int t = idx / QN, q = idx - t*QN;
        d_Yf[(size_t)(p0 + t)*QN + q] = Hs[hsw(q, t)];
    }
}

// ---- inverse X-FFT, warp per (b,ky,pair) ----------------------------------
__global__ __launch_bounds__(256) void k_ifftx(){
    int tid = threadIdx.x, wl = tid >> 5, l = tid & 31;
    int wid = blockIdx.x*8 + wl;
    int pr = wid % NPAIR;
    int ky = (wid / NPAIR) % YHN;
    int b  = wid / (NPAIR*YHN);
    Tw tw = make_tw(l);
    int q0 = b*WCH + 2*pr;
    float2 v[4], u[4];
    #pragma unroll
    for (int r = 0; r < 4; r++){
        int kxs = r*32 + l;
        float4 f = *(const float4*)(d_Yf + ((size_t)kxs*YHN + ky)*QN + q0);
        v[r] = make_float2(f.x, f.y);
        u[r] = make_float2(f.z, f.w);
    }
    fft_dit<true>(v, tw, l);
    fft_dit<true>(u, tw, l);
    float4* dst = d_Gy + (((size_t)b*YHN + ky)*NPAIR + pr)*XN;
    #pragma unroll
    for (int r = 0; r < 4; r++)
        dst[r*32 + l] = make_float4(v[r].x, v[r].y, u[r].x, u[r].y);
}

// ---- k_tail: inverse Y-rFFT + conv + h update + out proj + next Y-FFT -----
__global__ __launch_bounds__(384) void k_tail(const float* __restrict__ convw,
                                              const float* __restrict__ convb,
                                              const float* __restrict__ outw,
                                              const float* __restrict__ outb,
                                              float* __restrict__ out,
                                              int d, int t, int last, int do_fft){
    __shared__ float hrow [WCH*YN];   // [c][yb]
    __shared__ float x1row[YN*25];    // [yb][c]
    __shared__ float hn   [YN*25];    // [yb][c]
    __shared__ float cw[WCH*WCH];
    __shared__ float cb[WCH];
    __shared__ float ow[WCH];
    __shared__ float ob;
    int tid = threadIdx.x, wl = tid >> 5, l = tid & 31;
    int bx = blockIdx.x, b = bx >> 7, x = bx & 127;
    Tw tw = make_tw(l);
    float* hpb = d_h + (size_t)b*WCH*XN*YN + (size_t)x*YN;
    for (int idx = tid; idx < WCH*YN; idx += 384){
        int c = idx >> 7, y = idx & 127;
        hrow[idx] = hpb[(size_t)c*XN*YN + y];
    }
    for (int idx = tid; idx < WCH*WCH; idx += 384) cw[idx] = convw[d*WCH*WCH + idx];
    if (tid < WCH){ cb[tid] = convb[d*WCH + tid]; ow[tid] = outw[tid]; }
    if (tid == 0) ob = outb[0];
    // inverse Y (packed pair): warp wl = pair
    {
        int pr = wl;
        const float4* gy = d_Gy + ((size_t)b*YHN*NPAIR + pr)*XN + x;
        float2 z[4];
        {   // k = l (DC imag discarded at l==0)
            float4 f = gy[(size_t)l*NPAIR*XN];
            float2 g0 = make_float2(f.x, f.y), g1 = make_float2(f.z, f.w);
            if (l == 0){ g0.y = 0.f; g1.y = 0.f; }
            z[0] = make_float2(g0.x - g1.y, g0.y + g1.x);
        }
        {   // k = 32+l
            float4 f = gy[(size_t)(32+l)*NPAIR*XN];
            z[1] = make_float2(f.x - f.w, f.y + f.z);
        }
        {   // k = 64+l: l==0 direct (Nyquist); else mirror km=64-l
            int km = 64 - l;
            float4 f = gy[(size_t)km*NPAIR*XN];
            float2 g0 = make_float2(f.x, f.y), g1 = make_float2(f.z, f.w);
            if (l == 0){
                g0.y = 0.f; g1.y = 0.f;
                z[2] = make_float2(g0.x - g1.y, g0.y + g1.x);
            } else {
                z[2] = make_float2(g0.x + g1.y, g1.x - g0.y);
            }
        }
        {   // k = 96+l: mirror km = 32-l
            int km = 32 - l;
            float4 f = gy[(size_t)km*NPAIR*XN];
            z[3] = make_float2(f.x + f.w, f.z - f.y);
        }
        fft_dif<true>(z, tw, l);
        const float sc = 1.f/16384.f;
        #pragma unroll
        for (int r = 0; r < 4; r++){
            int p = r*32 + l;
            x1row[p*25 + 2*pr    ] = z[r].x * sc;
            x1row[p*25 + 2*pr + 1] = z[r].y * sc;
        }
    }
    __syncthreads();
    // conv + relu-combine: thread -> (y, o-group of 8)
    {
        int y = tid & 127, og = tid >> 7, o0 = og*8;
        float acc[8];
        #pragma unroll
        for (int j = 0; j < 8; j++) acc[j] = cb[o0 + j];
        #pragma unroll
        for (int i = 0; i < WCH; i++){
            float hv = hrow[i*YN + y];
            #pragma unroll
            for (int j = 0; j < 8; j++) acc[j] = fmaf(hv, cw[i*WCH + o0 + j], acc[j]);
        }
        #pragma unroll
        for (int j = 0; j < 8; j++){
            float v = x1row[y*25 + o0 + j];
            hn[y*25 + o0 + j] = fmaxf(v, 0.f) + acc[j];
        }
    }
    __syncthreads();
    for (int idx = tid; idx < WCH*YN; idx += 384){
        int c = idx >> 7, yy = idx & 127;
        hpb[(size_t)c*XN*YN + yy] = hn[yy*25 + c];
    }
    if (last){
        for (int yy = tid; yy < YN; yy += 384){
            float a = ob;
            #pragma unroll
            for (int c = 0; c < WCH; c++) a = fmaf(hn[yy*25 + c], ow[c], a);
            out[(((size_t)b*TSTEPS + t)*XN + x)*YN + brev7(yy)] = a;
        }
    }
    if (do_fft)
        ffty_pair(hn, b, x, wl, tw, l);
}

// ---------------------------------------------------------------------------
extern "C" void kernel_launch(void* const* d_in, const int* in_sizes, int n_in,
                              void* d_out, int out_size){
    (void)in_sizes; (void)n_in; (void)out_size;
    const float* x     = (const float*)d_in[0];
    const float* in_w  = (const float*)d_in[1];
    const float* in_b  = (const float*)d_in[2];
    const float2* specw= (const float2*)d_in[3];
    const float* convw = (const float*)d_in[4];
    const float* convb = (const float*)d_in[5];
    const float* outw  = (const float*)d_in[6];
    const float* outb  = (const float*)d_in[7];
    float* out = (float*)d_out;

    k_first<<<BN*XN, 384>>>(x, in_w, in_b);
    for (int t = 0; t < TSTEPS; t++){
        for (int d = 0; d < DL; d++){
            k_fftx <<<BN*YHN*NPAIR/8, 256>>>();
            k_spec <<<PTS/32        , 256>>>(specw, d);
            k_ifftx<<<BN*YHN*NPAIR/8, 256>>>();
            int last   = (d == DL-1);
            int do_fft = !(t == TSTEPS-1 && d == DL-1);
            k_tail <<<BN*XN         , 384>>>(convw, convb, outw, outb, out, d, t, last, do_fft);
        }
    }
}

// round 9
// speedup vs baseline: 1.9715x; 1.0046x over previous
#include <cuda_runtime.h>
#include <math.h>

#define BN 8
#define XN 128
#define YN 128
#define YHN 65
#define WCH 24
#define DL 4
#define TSTEPS 8
#define NPAIR 12
#define PTS (XN*YHN)       // 8320
#define QN (BN*WCH)        // 192

// Conventions: spatial y stored BIT-REVERSED (7-bit) in d_h.
// kx stored bit-reversed ("kxs") in d_Hf/d_Yf; k_spec maps weights via brev7.
// All global READS are coalesced; transposition scatters happen on WRITES.

__device__ float  d_h [BN*WCH*XN*YN];                  // [b][c][x][yb]
__device__ __align__(16) float4 d_Hy[BN*YHN*NPAIR*XN]; // [b][ky][pair][x]
__device__ __align__(16) float2 d_Hf[PTS*QN];          // [(kxs*65+ky)][q]
__device__ __align__(16) float4 d_Yf[BN*YHN*NPAIR*XN]; // [b][ky][pair][kxs]
__device__ __align__(16) float4 d_Gy[BN*NPAIR*XN*YHN]; // [b][pair][x][ky]

__device__ __forceinline__ float2 cmul(float2 a, float2 b){
    return make_float2(fmaf(a.x,b.x,-a.y*b.y), fmaf(a.x,b.y, a.y*b.x));
}
__device__ __forceinline__ float2 cadd(float2 a, float2 b){ return make_float2(a.x+b.x, a.y+b.y); }
__device__ __forceinline__ float2 csub(float2 a, float2 b){ return make_float2(a.x-b.x, a.y-b.y); }

struct Tw { float2 w1, w1b, w2, w4, w8, w16, w32; };

template<bool INV>
__device__ __forceinline__ float2 tsel(float2 w){ return INV ? make_float2(w.x, -w.y) : w; }

__device__ __forceinline__ Tw make_tw(int l){
    Tw t; float s, c;
    const float P = -6.2831853071795864769f;
    sincosf(P*(float)l/128.f, &s, &c);       t.w1  = make_float2(c, s);
    t.w1b = make_float2(t.w1.y, -t.w1.x);
    t.w2  = cmul(t.w1, t.w1);
    sincosf(P*(float)(l&15)/32.f, &s, &c);   t.w4  = make_float2(c, s);
    sincosf(P*(float)(l&7)/16.f,  &s, &c);   t.w8  = make_float2(c, s);
    sincosf(P*(float)(l&3)/8.f,   &s, &c);   t.w16 = make_float2(c, s);
    t.w32 = (l&1) ? make_float2(0.f, -1.f) : make_float2(1.f, 0.f);
    return t;
}

__device__ __forceinline__ void dif_x4(float2 v[4], int m, float2 w, int l){
    #pragma unroll
    for (int r = 0; r < 4; r++){
        float2 p;
        p.x = __shfl_xor_sync(0xffffffffu, v[r].x, m);
        p.y = __shfl_xor_sync(0xffffffffu, v[r].y, m);
        v[r] = (l & m) ? cmul(csub(p, v[r]), w) : cadd(v[r], p);
    }
}
__device__ __forceinline__ void dit_x4(float2 v[4], int m, float2 w, int l){
    #pragma unroll
    for (int r = 0; r < 4; r++){
        float2 b = (l & m) ? cmul(v[r], w) : v[r];
        float2 p;
        p.x = __shfl_xor_sync(0xffffffffu, b.x, m);
        p.y = __shfl_xor_sync(0xffffffffu, b.y, m);
        v[r] = (l & m) ? csub(p, b) : cadd(b, p);
    }
}

template<bool INV>
__device__ __forceinline__ void fft_dif(float2 v[4], const Tw& t, int l){
    const float2 one = make_float2(1.f, 0.f);
    float2 w1 = tsel<INV>(t.w1), w1b = tsel<INV>(t.w1b), w2 = tsel<INV>(t.w2);
    float2 tm;
    tm = csub(v[0], v[2]); v[0] = cadd(v[0], v[2]); v[2] = cmul(tm, w1);
    tm = csub(v[1], v[3]); v[1] = cadd(v[1], v[3]); v[3] = cmul(tm, w1b);
    tm = csub(v[0], v[1]); v[0] = cadd(v[0], v[1]); v[1] = cmul(tm, w2);
    tm = csub(v[2], v[3]); v[2] = cadd(v[2], v[3]); v[3] = cmul(tm, w2);
    dif_x4(v, 16, tsel<INV>(t.w4),  l);
    dif_x4(v,  8, tsel<INV>(t.w8),  l);
    dif_x4(v,  4, tsel<INV>(t.w16), l);
    dif_x4(v,  2, tsel<INV>(t.w32), l);
    dif_x4(v,  1, one, l);
}

template<bool INV>
__device__ __forceinline__ void fft_dit(float2 v[4], const Tw& t, int l){
    const float2 one = make_float2(1.f, 0.f);
    dit_x4(v,  1, one, l);
    dit_x4(v,  2, tsel<INV>(t.w32), l);
    dit_x4(v,  4, tsel<INV>(t.w16), l);
    dit_x4(v,  8, tsel<INV>(t.w8),  l);
    dit_x4(v, 16, tsel<INV>(t.w4),  l);
    float2 w1 = tsel<INV>(t.w1), w1b = tsel<INV>(t.w1b), w2 = tsel<INV>(t.w2);
    float2 b;
    b = cmul(v[1], w2);  v[1] = csub(v[0], b); v[0] = cadd(v[0], b);
    b = cmul(v[3], w2);  v[3] = csub(v[2], b); v[2] = cadd(v[2], b);
    b = cmul(v[2], w1);  v[2] = csub(v[0], b); v[0] = cadd(v[0], b);
    b = cmul(v[3], w1b); v[3] = csub(v[1], b); v[1] = cadd(v[1], b);
}

__device__ __forceinline__ int brev7(int i){ return (int)(__brev((unsigned)i) >> 25); }

// Forward packed Y-FFT of one channel pair from smem row hn[yb*25 + c], write d_Hy.
__device__ __forceinline__ void ffty_pair(const float* hn, int b, int x, int pr,
                                          const Tw& tw, int l){
    float2 v[4];
    #pragma unroll
    for (int r = 0; r < 4; r++){
        int p = r*32 + l;
        v[r] = make_float2(hn[p*25 + 2*pr], hn[p*25 + 2*pr + 1]);
    }
    fft_dit<false>(v, tw, l);                     // natural ky = r*32+l
    int srcl = (32 - l) & 31;
    float2 s3, s2;
    s3.x = __shfl_sync(0xffffffffu, v[3].x, srcl);
    s3.y = __shfl_sync(0xffffffffu, v[3].y, srcl);
    s2.x = __shfl_sync(0xffffffffu, v[2].x, srcl);
    s2.y = __shfl_sync(0xffffffffu, v[2].y, srcl);
    float2 zm0 = (l == 0) ? v[0] : s3;            // partner of ky=l
    float2 zm1 = (l == 0) ? s3   : s2;            // partner of ky=32+l
    float4* hy = d_Hy + ((size_t)b*YHN*NPAIR + pr)*XN + x;
    float2 zk;
    zk = v[0];                                    // ky = l
    hy[(size_t)l*NPAIR*XN] = make_float4(
        0.5f*(zk.x+zm0.x), 0.5f*(zk.y-zm0.y),
        0.5f*(zk.y+zm0.y), 0.5f*(zm0.x-zk.x));
    zk = v[1];                                    // ky = 32+l
    hy[(size_t)(32+l)*NPAIR*XN] = make_float4(
        0.5f*(zk.x+zm1.x), 0.5f*(zk.y-zm1.y),
        0.5f*(zk.y+zm1.y), 0.5f*(zm1.x-zk.x));
    if (l == 0){                                  // ky = 64
        zk = v[2];
        hy[(size_t)64*NPAIR*XN] = make_float4(zk.x, 0.f, zk.y, 0.f);
    }
}

// ---------------- k_first: h0 = x@in_w+in_b (bitrev-y) + forward Y-FFT ------
__global__ __launch_bounds__(384) void k_first(const float* __restrict__ xin,
                                               const float* __restrict__ inw,
                                               const float* __restrict__ inb){
    __shared__ float2 xv[XN];
    __shared__ float  hn[YN*25];
    int tid = threadIdx.x, wl = tid >> 5, l = tid & 31;
    int bx = blockIdx.x, b = bx >> 7, x = bx & 127;
    if (tid < XN)
        xv[tid] = *(const float2*)(xin + (((size_t)(b*XN + x))*YN + tid)*2);
    __syncthreads();
    for (int idx = tid; idx < WCH*YN; idx += 384){
        int c = idx >> 7, yb = idx & 127;
        float2 v = xv[brev7(yb)];
        float val = inb[c] + v.x*inw[c] + v.y*inw[WCH + c];
        hn[yb*25 + c] = val;
        d_h[((size_t)(b*WCH + c)*XN + x)*YN + yb] = val;
    }
    __syncthreads();
    Tw tw = make_tw(l);
    ffty_pair(hn, b, x, wl, tw, l);
}

// ---- X-FFT (complex, both channels), warp per (b,ky,pair) -----------------
__global__ __launch_bounds__(256) void k_fftx(){
    int tid = threadIdx.x, wl = tid >> 5, l = tid & 31;
    int wid = blockIdx.x*8 + wl;
    int pr = wid % NPAIR;
    int ky = (wid / NPAIR) % YHN;
    int b  = wid / (NPAIR*YHN);
    Tw tw = make_tw(l);
    const float4* src = d_Hy + (((size_t)b*YHN + ky)*NPAIR + pr)*XN;
    float2 v[4], u[4];
    #pragma unroll
    for (int r = 0; r < 4; r++){
        float4 f = src[r*32 + l];
        v[r] = make_float2(f.x, f.y);
        u[r] = make_float2(f.z, f.w);
    }
    fft_dif<false>(v, tw, l);
    fft_dif<false>(u, tw, l);
    int q0 = b*WCH + 2*pr;
    #pragma unroll
    for (int r = 0; r < 4; r++){
        int kxs = r*32 + l;
        *(float4*)(d_Hf + ((size_t)kxs*YHN + ky)*QN + q0)
            = make_float4(v[r].x, v[r].y, u[r].x, u[r].y);
    }
}

// ---------------- per-point complex channel mix ----------------------------
__device__ __forceinline__ int hsw(int q, int t){ return q*32 + ((t + q) & 31); }

__global__ __launch_bounds__(256) void k_spec(const float2* __restrict__ specw, int d){
    __shared__ float2 Hs[QN*32];
    int tid = threadIdx.x;
    int p0 = blockIdx.x * 32;
    for (int idx = tid; idx < 32*QN; idx += 256){
        int t = idx / QN, q = idx - t*QN;
        Hs[hsw(q, t)] = d_Hf[(size_t)(p0 + t)*QN + q];
    }
    __syncthreads();
    int w = tid >> 5, lane = tid & 31;
    int p   = p0 + lane;
    int kxs = p / 65;
    int ky  = p - kxs*65;
    int pb  = brev7(kxs)*65 + ky;                 // true weight column
    const float2* wp = specw + (size_t)(d*576)*PTS + pb;
    float2 acc0[8], acc1[8], acc2[8];
    #pragma unroll
    for (int bb = 0; bb < 8; bb++){
        acc0[bb] = make_float2(0.f,0.f);
        acc1[bb] = make_float2(0.f,0.f);
        acc2[bb] = make_float2(0.f,0.f);
    }
    // software pipeline, depth 2
    float2 wv0 = wp[(size_t)(0*WCH + w     )*PTS];
    float2 wv1 = wp[(size_t)(0*WCH + w +  8)*PTS];
    float2 wv2 = wp[(size_t)(0*WCH + w + 16)*PTS];
    float2 pv0 = wp[(size_t)(1*WCH + w     )*PTS];
    float2 pv1 = wp[(size_t)(1*WCH + w +  8)*PTS];
    float2 pv2 = wp[(size_t)(1*WCH + w + 16)*PTS];
    for (int i = 0; i < WCH; i++){
        int ip = (i + 2 < WCH) ? i + 2 : WCH - 1;
        float2 qv0 = wp[(size_t)(ip*WCH + w     )*PTS];
        float2 qv1 = wp[(size_t)(ip*WCH + w +  8)*PTS];
        float2 qv2 = wp[(size_t)(ip*WCH + w + 16)*PTS];
        float2 hv[8];
        #pragma unroll
        for (int bb = 0; bb < 8; bb++) hv[bb] = Hs[hsw(bb*WCH + i, lane)];
        #pragma unroll
        for (int bb = 0; bb < 8; bb++){
            acc0[bb].x = fmaf( hv[bb].x, wv0.x, acc0[bb].x);
            acc0[bb].x = fmaf(-hv[bb].y, wv0.y, acc0[bb].x);
            acc0[bb].y = fmaf( hv[bb].x, wv0.y, acc0[bb].y);
            acc0[bb].y = fmaf( hv[bb].y, wv0.x, acc0[bb].y);
            acc1[bb].x = fmaf( hv[bb].x, wv1.x, acc1[bb].x);
            acc1[bb].x = fmaf(-hv[bb].y, wv1.y, acc1[bb].x);
            acc1[bb].y = fmaf( hv[bb].x, wv1.y, acc1[bb].y);
            acc1[bb].y = fmaf( hv[bb].y, wv1.x, acc1[bb].y);
            acc2[bb].x = fmaf( hv[bb].x, wv2.x, acc2[bb].x);
            acc2[bb].x = fmaf(-hv[bb].y, wv2.y, acc2[bb].x);
            acc2[bb].y = fmaf( hv[bb].x, wv2.y, acc2[bb].y);
            acc2[bb].y = fmaf( hv[bb].y, wv2.x, acc2[bb].y);
        }
        wv0 = pv0; wv1 = pv1; wv2 = pv2;
        pv0 = qv0; pv1 = qv1; pv2 = qv2;
    }
    __syncthreads();
    #pragma unroll
    for (int bb = 0; bb < 8; bb++){
        Hs[hsw(bb*WCH + w     , lane)] = acc0[bb];
        Hs[hsw(bb*WCH + w +  8, lane)] = acc1[bb];
        Hs[hsw(bb*WCH + w + 16, lane)] = acc2[bb];
    }
    __syncthreads();
    // transposed scatter-write: d_Yf[b][ky][pair][kxs] (paired channels packed)
    for (int idx = tid; idx < 32*(QN/2); idx += 256){
        int j = idx >> 5, t = idx & 31;           // j = b*12+pr
        int b = j / NPAIR, pr = j - b*NPAIR;
        int pp  = p0 + t;
        int kxs2 = pp / 65;
        int ky2  = pp - kxs2*65;
        float2 a = Hs[hsw(b*WCH + 2*pr    , t)];
        float2 c = Hs[hsw(b*WCH + 2*pr + 1, t)];
        d_Yf[(((size_t)b*YHN + ky2)*NPAIR + pr)*XN + kxs2]
            = make_float4(a.x, a.y, c.x, c.y);
    }
}

// ---- inverse X-FFT, warp per (b,ky,pair): coalesced read, scattered write --
__global__ __launch_bounds__(256) void k_ifftx(){
    int tid = threadIdx.x, wl = tid >> 5, l = tid & 31;
    int wid = blockIdx.x*8 + wl;
    int pr = wid % NPAIR;
    int ky = (wid / NPAIR) % YHN;
    int b  = wid / (NPAIR*YHN);
    Tw tw = make_tw(l);
    const float4* src = d_Yf + (((size_t)b*YHN + ky)*NPAIR + pr)*XN;
    float2 v[4], u[4];
    #pragma unroll
    for (int r = 0; r < 4; r++){
        float4 f = src[r*32 + l];                 // contiguous 2KB per warp
        v[r] = make_float2(f.x, f.y);
        u[r] = make_float2(f.z, f.w);
    }
    fft_dit<true>(v, tw, l);
    fft_dit<true>(u, tw, l);
    float4* dst = d_Gy + (((size_t)b*NPAIR + pr)*XN)*YHN + ky;  // + x*YHN
    #pragma unroll
    for (int r = 0; r < 4; r++){
        int x = r*32 + l;
        dst[(size_t)x*YHN] = make_float4(v[r].x, v[r].y, u[r].x, u[r].y);
    }
}

// ---- k_tail: inverse Y-rFFT + conv + h update + out proj + next Y-FFT -----
__global__ __launch_bounds__(384) void k_tail(const float* __restrict__ convw,
                                              const float* __restrict__ convb,
                                              const float* __restrict__ outw,
                                              const float* __restrict__ outb,
                                              float* __restrict__ out,
                                              int d, int t, int last, int do_fft){
    __shared__ float hrow [WCH*YN];   // [c][yb]
    __shared__ float x1row[YN*25];    // [yb][c]
    __shared__ float hn   [YN*25];    // [yb][c]
    __shared__ float cw[WCH*WCH];
    __shared__ float cb[WCH];
    __shared__ float ow[WCH];
    __shared__ float ob;
    int tid = threadIdx.x, wl = tid >> 5, l = tid & 31;
    int bx = blockIdx.x, b = bx >> 7, x = bx & 127;
    Tw tw = make_tw(l);
    float* hpb = d_h + (size_t)b*WCH*XN*YN + (size_t)x*YN;
    for (int idx = tid; idx < WCH*YN; idx += 384){
        int c = idx >> 7, y = idx & 127;
        hrow[idx] = hpb[(size_t)c*XN*YN + y];
    }
    for (int idx = tid; idx < WCH*WCH; idx += 384) cw[idx] = convw[d*WCH*WCH + idx];
    if (tid < WCH){ cb[tid] = convb[d*WCH + tid]; ow[tid] = outw[tid]; }
    if (tid == 0) ob = outb[0];
    // inverse Y (packed pair): warp wl = pair; coalesced d_Gy rows
    {
        int pr = wl;
        const float4* gy = d_Gy + (((size_t)b*NPAIR + pr)*XN + x)*YHN;
        float2 z[4];
        {   // k = l (DC imag discarded at l==0)
            float4 f = gy[l];
            float2 g0 = make_float2(f.x, f.y), g1 = make_float2(f.z, f.w);
            if (l == 0){ g0.y = 0.f; g1.y = 0.f; }
            z[0] = make_float2(g0.x - g1.y, g0.y + g1.x);
        }
        {   // k = 32+l
            float4 f = gy[32 + l];
            z[1] = make_float2(f.x - f.w, f.y + f.z);
        }
        {   // k = 64+l: l==0 direct (Nyquist); else mirror km=64-l
            int km = 64 - l;
            float4 f = gy[km];
            float2 g0 = make_float2(f.x, f.y), g1 = make_float2(f.z, f.w);
            if (l == 0){
                g0.y = 0.f; g1.y = 0.f;
                z[2] = make_float2(g0.x - g1.y, g0.y + g1.x);
            } else {
                z[2] = make_float2(g0.x + g1.y, g1.x - g0.y);
            }
        }
        {   // k = 96+l: mirror km = 32-l
            int km = 32 - l;
            float4 f = gy[km];
            z[3] = make_float2(f.x + f.w, f.z - f.y);
        }
        fft_dif<true>(z, tw, l);
        const float sc = 1.f/16384.f;
        #pragma unroll
        for (int r = 0; r < 4; r++){
            int p = r*32 + l;
            x1row[p*25 + 2*pr    ] = z[r].x * sc;
            x1row[p*25 + 2*pr + 1] = z[r].y * sc;
        }
    }
    __syncthreads();
    // conv + relu-combine: thread -> (y, o-group of 8)
    {
        int y = tid & 127, og = tid >> 7, o0 = og*8;
        float acc[8];
        #pragma unroll
        for (int j = 0; j < 8; j++) acc[j] = cb[o0 + j];
        #pragma unroll
        for (int i = 0; i < WCH; i++){
            float hv = hrow[i*YN + y];
            #pragma unroll
            for (int j = 0; j < 8; j++) acc[j] = fmaf(hv, cw[i*WCH + o0 + j], acc[j]);
        }
        #pragma unroll
        for (int j = 0; j < 8; j++){
            float v = x1row[y*25 + o0 + j];
            hn[y*25 + o0 + j] = fmaxf(v, 0.f) + acc[j];
        }
    }
    __syncthreads();
    for (int idx = tid; idx < WCH*YN; idx += 384){
        int c = idx >> 7, yy = idx & 127;
        hpb[(size_t)c*XN*YN + yy] = hn[yy*25 + c];
    }
    if (last){
        for (int yy = tid; yy < YN; yy += 384){
            float a = ob;
            #pragma unroll
            for (int c = 0; c < WCH; c++) a = fmaf(hn[yy*25 + c], ow[c], a);
            out[(((size_t)b*TSTEPS + t)*XN + x)*YN + brev7(yy)] = a;
        }
    }
    if (do_fft)
        ffty_pair(hn, b, x, wl, tw, l);
}

// ---------------------------------------------------------------------------
extern "C" void kernel_launch(void* const* d_in, const int* in_sizes, int n_in,
                              void* d_out, int out_size){
    (void)in_sizes; (void)n_in; (void)out_size;
    const float* x     = (const float*)d_in[0];
    const float* in_w  = (const float*)d_in[1];
    const float* in_b  = (const float*)d_in[2];
    const float2* specw= (const float2*)d_in[3];
    const float* convw = (const float*)d_in[4];
    const float* convb = (const float*)d_in[5];
    const float* outw  = (const float*)d_in[6];
    const float* outb  = (const float*)d_in[7];
    float* out = (float*)d_out;

    k_first<<<BN*XN, 384>>>(x, in_w, in_b);
    for (int t = 0; t < TSTEPS; t++){
        for (int d = 0; d < DL; d++){
            k_fftx <<<BN*YHN*NPAIR/8, 256>>>();
            k_spec <<<PTS/32        , 256>>>(specw, d);
            k_ifftx<<<BN*YHN*NPAIR/8, 256>>>();
            int last   = (d == DL-1);
            int do_fft = !(t == TSTEPS-1 && d == DL-1);
            k_tail <<<BN*XN         , 384>>>(convw, convb, outw, outb, out, d, t, last, do_fft);
        }
    }
}